// round 1
// baseline (speedup 1.0000x reference)
#include <cuda_runtime.h>

#define TN (1 << 20)
#define LOG2TN 20
#define TQ (TN >> 2)
#define KM 3
#define C_ALPHA 2000.0f
#define C_TAU 1e-7f
#define C_TAU2 1e-14f
#define C_EPS 1e-8f
#define PI_D 3.14159265358979323846

// ---------------- scratch (device globals; no allocation allowed) ----------------
__device__ float2 g_A[3 * TN];      // FFT ping buffer / final u
__device__ float2 g_Bb[3 * TN];     // FFT pong buffer
__device__ float2 g_fhat[TN];       // fftshift(fft(x))
__device__ float2 g_lam[2][TN];     // lambda ping-pong (parity = n&1 reads g_lam[n&1])
__device__ double g_acc[8];         // [0..2]=sum power_k, [3..5]=sum power_k*freq, [6]=diff_num, [7]=diff_den
__device__ float  g_om[KM];
__device__ float  g_omPrev[KM];
__device__ int    g_done;
__device__ int    g_lastPar;

// ---------------- complex helpers ----------------
__device__ __forceinline__ float2 cadd(float2 a, float2 b) { return make_float2(a.x + b.x, a.y + b.y); }
__device__ __forceinline__ float2 csub(float2 a, float2 b) { return make_float2(a.x - b.x, a.y - b.y); }
__device__ __forceinline__ float2 cmul(float2 a, float2 b) {
    return make_float2(a.x * b.x - a.y * b.y, a.x * b.y + a.y * b.x);
}

// ---------------- init ----------------
__global__ void init_kernel(const float* __restrict__ om0) {
    int t = blockIdx.x * blockDim.x + threadIdx.x;
    if (t < TN) g_lam[0][t] = make_float2(0.f, 0.f);
    if (t < KM) { float v = 0.5f * om0[t]; g_om[t] = v; g_omPrev[t] = v; }
    if (t == 0) {
        g_done = 0; g_lastPar = 0;
        for (int i = 0; i < 8; i++) g_acc[i] = 0.0;
    }
}

// y[n] = (-1)^n x[n]  (implements fftshift on the output spectrum)
__global__ void pack_kernel(const float* __restrict__ x) {
    int t = blockIdx.x * blockDim.x + threadIdx.x;
    float v = x[t];
    g_A[t] = make_float2((t & 1) ? -v : v, 0.f);
}

// ---------------- radix-4 Stockham FFT stage (batched) ----------------
// stage i: s = 4^i, m = TN/4^(i+1), theta0 = -+2*pi/(TN/4^i)
template <bool FWD>
__global__ void fft_stage(int inIsB, int log2s, int m, float th0) {
    int gid  = blockIdx.x * blockDim.x + threadIdx.x;
    int tid  = gid & (TQ - 1);
    int base = (gid >> (LOG2TN - 2)) << LOG2TN;   // batch * TN
    const float2* __restrict__ X = (inIsB ? g_Bb : g_A) + base;
    float2* __restrict__       Y = (inIsB ? g_A : g_Bb) + base;
    int s_ = 1 << log2s;
    int q  = tid & (s_ - 1);
    int p  = tid >> log2s;

    float2 a = X[q + ((p        ) << log2s)];
    float2 b = X[q + ((p +     m) << log2s)];
    float2 c = X[q + ((p + 2 * m) << log2s)];
    float2 d = X[q + ((p + 3 * m) << log2s)];

    float2 apc = cadd(a, c), amc = csub(a, c);
    float2 bpd = cadd(b, d), bmd = csub(b, d);

    float ang = th0 * (float)p;
    float sn, cs;
    sincosf(ang, &sn, &cs);
    float2 w1 = make_float2(cs, sn);
    float2 w2 = cmul(w1, w1);
    float2 w3 = cmul(w2, w1);

    float2 t1, t3;
    if (FWD) {  // omega4 = -i
        t1 = make_float2(amc.x + bmd.y, amc.y - bmd.x);
        t3 = make_float2(amc.x - bmd.y, amc.y + bmd.x);
    } else {    // omega4 = +i
        t1 = make_float2(amc.x - bmd.y, amc.y + bmd.x);
        t3 = make_float2(amc.x + bmd.y, amc.y - bmd.x);
    }
    int ob = (4 * p) << log2s;
    Y[q + ob         ] = cadd(apc, bpd);
    Y[q + ob +     s_] = cmul(t1, w1);
    Y[q + ob + 2 * s_] = cmul(csub(apc, bpd), w2);
    Y[q + ob + 3 * s_] = cmul(t3, w3);
}

__global__ void copy_fhat_kernel() {
    int t = blockIdx.x * blockDim.x + threadIdx.x;
    g_fhat[t] = g_A[t];
}

// ---------------- u update (shared by iterate / u_prev recompute / final) ----------------
__device__ __forceinline__ void compute_u(float fr, float2 fh, float2 la,
                                          float om0, float om1, float om2,
                                          float2& u0, float2& u1, float2& u2) {
    float nr = fh.x - 0.5f * la.x;
    float ni = fh.y - 0.5f * la.y;
    float d0 = fr - om0; d0 *= d0;
    float d1 = fr - om1; d1 *= d1;
    float d2 = fr - om2; d2 *= d2;
    float e0 = (d0 + C_TAU2) + d1;
    float e1 = ((d1 + C_TAU2) + d0) + d2;
    float e2 = (d2 + C_TAU2) + d1;
    float g0 = 1.0f / (1.0f + C_ALPHA * e0);
    float g1 = 1.0f / (1.0f + C_ALPHA * e1);
    float g2 = 1.0f / (1.0f + C_ALPHA * e2);
    u0 = make_float2(nr * g0, ni * g0);
    u1 = make_float2(nr * g1, ni * g1);
    u2 = make_float2(nr * g2, ni * g2);
}

#define ITER_BLOCKS 1024
#define ITER_TPB 256
#define ITER_STRIDE (ITER_BLOCKS * ITER_TPB)   // 262144; 4 elems/thread

__global__ void __launch_bounds__(ITER_TPB) iterate_kernel(int srcP, int doDiff) {
    if (g_done) return;   // frozen: whole-block uniform early out
    int tid0 = blockIdx.x * blockDim.x + threadIdx.x;
    float om0 = g_om[0], om1 = g_om[1], om2 = g_om[2];
    float q0 = g_omPrev[0], q1 = g_omPrev[1], q2 = g_omPrev[2];
    const float2* __restrict__ lamIn = g_lam[srcP];
    float2* __restrict__ lamOut = g_lam[srcP ^ 1];

    float vals[8];
#pragma unroll
    for (int i = 0; i < 8; i++) vals[i] = 0.f;

#pragma unroll
    for (int it = 0; it < 4; it++) {
        int t = tid0 + it * ITER_STRIDE;
        float fr = (float)t * (1.0f / 1048576.0f) - 0.5f;
        float2 fh = g_fhat[t];
        float2 la = lamIn[t];
        float2 u0, u1, u2;
        compute_u(fr, fh, la, om0, om1, om2, u0, u1, u2);

        float p0 = u0.x * u0.x + u0.y * u0.y;
        float p1 = u1.x * u1.x + u1.y * u1.y;
        float p2 = u2.x * u2.x + u2.y * u2.y;

        float2 ln = make_float2(la.x + C_TAU * ((u0.x + u1.x + u2.x) - fh.x),
                                la.y + C_TAU * ((u0.y + u1.y + u2.y) - fh.y));

        if (doDiff) {
            // u_prev = f(lambda entering step n-1, omega entering step n-1)
            float2 lp = lamOut[t];   // old content of the buffer we're about to overwrite
            float2 v0, v1, v2;
            compute_u(fr, fh, lp, q0, q1, q2, v0, v1, v2);
            float dn = (u0.x - v0.x) * (u0.x - v0.x) + (u0.y - v0.y) * (u0.y - v0.y)
                     + (u1.x - v1.x) * (u1.x - v1.x) + (u1.y - v1.y) * (u1.y - v1.y)
                     + (u2.x - v2.x) * (u2.x - v2.x) + (u2.y - v2.y) * (u2.y - v2.y);
            float dd = v0.x * v0.x + v0.y * v0.y + v1.x * v1.x + v1.y * v1.y
                     + v2.x * v2.x + v2.y * v2.y;
            vals[6] += dn;
            vals[7] += dd;
        }
        lamOut[t] = ln;

        vals[0] += p0; vals[1] += p1; vals[2] += p2;
        vals[3] += p0 * fr; vals[4] += p1 * fr; vals[5] += p2 * fr;
    }

    // block reduce 8 accumulators -> double atomics
#pragma unroll
    for (int i = 0; i < 8; i++) {
        float v = vals[i];
#pragma unroll
        for (int o = 16; o > 0; o >>= 1) v += __shfl_down_sync(0xffffffffu, v, o);
        vals[i] = v;
    }
    __shared__ float sred[8][8];
    int wid = threadIdx.x >> 5, lid = threadIdx.x & 31;
    if (lid == 0) {
#pragma unroll
        for (int i = 0; i < 8; i++) sred[i][wid] = vals[i];
    }
    __syncthreads();
    if (threadIdx.x < 8) {
        double s = 0.0;
#pragma unroll
        for (int w = 0; w < 8; w++) s += (double)sred[threadIdx.x][w];
        atomicAdd(&g_acc[threadIdx.x], s);
    }
}

__global__ void finalize_kernel(int n) {
    if (threadIdx.x != 0 || blockIdx.x != 0) return;
    if (!g_done) {
        double sp0 = g_acc[0], sp1 = g_acc[1], sp2 = g_acc[2];
        float on0 = (float)(g_acc[3] / (sp0 + (double)C_EPS));
        float on1 = (float)(g_acc[4] / (sp1 + (double)C_EPS));
        float on2 = (float)(g_acc[5] / (sp2 + (double)C_EPS));
        float odiff = (fabsf(on0 - on2) + fabsf(on1 - on0) + fabsf(on2 - on1)) * (1.0f / 3.0f);
        double udiff = (n == 0) ? (sp0 + sp1 + sp2) / (double)C_EPS
                                : g_acc[6] / (g_acc[7] + (double)C_EPS);
        g_omPrev[0] = g_om[0]; g_omPrev[1] = g_om[1]; g_omPrev[2] = g_om[2];
        g_om[0] = on0; g_om[1] = on1; g_om[2] = on2;
        g_lastPar = n & 1;
        if ((n % 10 == 0) && (udiff < 1e-6) && (odiff < 1e-6f)) g_done = 1;
    }
    for (int i = 0; i < 8; i++) g_acc[i] = 0.0;
}

// final u = f(lambda entering last executed step, omega entering last executed step)
__global__ void ufinal_kernel() {
    int t = blockIdx.x * blockDim.x + threadIdx.x;
    int par = g_lastPar;
    float2 fh = g_fhat[t];
    float2 la = g_lam[par][t];
    float fr = (float)t * (1.0f / 1048576.0f) - 0.5f;
    float2 u0, u1, u2;
    compute_u(fr, fh, la, g_omPrev[0], g_omPrev[1], g_omPrev[2], u0, u1, u2);
    g_A[t] = u0;
    g_A[TN + t] = u1;
    g_A[2 * TN + t] = u2;
}

// imfs[k,n] = (-1)^n * Re(ifft(u_k))[n],  ifft scale 1/TN applied here
__global__ void out_kernel(float* __restrict__ out) {
    int i = blockIdx.x * blockDim.x + threadIdx.x;
    int t = i & (TN - 1);
    float s = (t & 1) ? -(1.0f / 1048576.0f) : (1.0f / 1048576.0f);
    out[i] = g_A[i].x * s;
}

// ---------------- launch ----------------
extern "C" void kernel_launch(void* const* d_in, const int* in_sizes, int n_in,
                              void* d_out, int out_size) {
    const float* x   = (const float*)d_in[0];
    const float* om0 = (const float*)d_in[1];
    float* out = (float*)d_out;

    init_kernel<<<TN / 256, 256>>>(om0);
    pack_kernel<<<TN / 256, 256>>>(x);

    // forward FFT of (-1)^n x : 10 radix-4 stages, result lands in g_A
    for (int i = 0; i < 10; i++) {
        double nlen = (double)(TN >> (2 * i));
        float th0 = (float)(-2.0 * PI_D / nlen);
        fft_stage<true><<<TQ / 256, 256>>>(i & 1, 2 * i, TN >> (2 * i + 2), th0);
    }
    copy_fhat_kernel<<<TN / 256, 256>>>();

    for (int n = 0; n < 50; n++) {
        int doDiff = (n > 0 && (n % 10) == 0) ? 1 : 0;
        iterate_kernel<<<ITER_BLOCKS, ITER_TPB>>>(n & 1, doDiff);
        finalize_kernel<<<1, 1>>>(n);
    }

    ufinal_kernel<<<TN / 256, 256>>>();

    // inverse FFT (batch K=3): 10 radix-4 stages with conjugate twiddles, result in g_A
    for (int i = 0; i < 10; i++) {
        double nlen = (double)(TN >> (2 * i));
        float th0 = (float)(2.0 * PI_D / nlen);
        fft_stage<false><<<3 * TQ / 256, 256>>>(i & 1, 2 * i, TN >> (2 * i + 2), th0);
    }
    out_kernel<<<3 * TN / 256, 256>>>(out);
}

// round 2
// speedup vs baseline: 1.1992x; 1.1992x over previous
#include <cuda_runtime.h>

#define TN (1 << 20)
#define LOG2TN 20
#define KM 3
#define C_ALPHA 2000.0f
#define C_TAU 1e-7f
#define C_TAU2 1e-14f
#define PI_D 3.14159265358979323846

// ---------------- scratch (device globals; no allocation allowed) ----------------
__device__ float2 g_A[3 * TN];       // FFT ping buffer (fwd input, u for inverse)
__device__ float2 g_Bb[3 * TN];      // FFT pong buffer (fhat after fwd, final after inv)
__device__ float2 g_lamPrev[TN];     // lambda stash for convergence diff
__device__ double g_accM[8];         // monotone accumulators
__device__ unsigned int g_ctr;       // barrier arrival counter (monotone)
__device__ float  g_om[KM];

// ---------------- complex helpers ----------------
__device__ __forceinline__ float2 cadd(float2 a, float2 b) { return make_float2(a.x + b.x, a.y + b.y); }
__device__ __forceinline__ float2 csub(float2 a, float2 b) { return make_float2(a.x - b.x, a.y - b.y); }
__device__ __forceinline__ float2 cmul(float2 a, float2 b) {
    return make_float2(a.x * b.x - a.y * b.y, a.x * b.y + a.y * b.x);
}

// ---------------- init ----------------
__global__ void init_kernel(const float* __restrict__ om0) {
    int t = threadIdx.x;
    if (t < KM) g_om[t] = 0.5f * om0[t];
    if (t < 8) g_accM[t] = 0.0;
    if (t == 0) g_ctr = 0u;
}

// y[n] = (-1)^n x[n]  (fftshift of the spectrum as a sign flip)
__global__ void pack_kernel(const float* __restrict__ x) {
    int t = blockIdx.x * blockDim.x + threadIdx.x;
    float v = x[t];
    g_A[t] = make_float2((t & 1) ? -v : v, 0.f);
}

// ---------------- radix-16 butterfly (4x4 four-step, constant twiddles) ----------------
template <bool FWD>
__device__ __forceinline__ void bf4(float2 a, float2 b, float2 c, float2 d,
                                    float2& o0, float2& o1, float2& o2, float2& o3) {
    float2 apc = cadd(a, c), amc = csub(a, c);
    float2 bpd = cadd(b, d), bmd = csub(b, d);
    o0 = cadd(apc, bpd);
    o2 = csub(apc, bpd);
    if (FWD) {  // w4 = -i
        o1 = make_float2(amc.x + bmd.y, amc.y - bmd.x);
        o3 = make_float2(amc.x - bmd.y, amc.y + bmd.x);
    } else {    // w4 = +i
        o1 = make_float2(amc.x - bmd.y, amc.y + bmd.x);
        o3 = make_float2(amc.x + bmd.y, amc.y - bmd.x);
    }
}

template <bool FWD>
__device__ __forceinline__ void fft16(float2* z) {
    const float S  = FWD ? -1.f : 1.f;
    const float C1 = 0.92387953251128674f;   // cos(pi/8)
    const float S1 = 0.38268343236508977f;   // sin(pi/8)
    const float R  = 0.70710678118654752f;   // sqrt(2)/2
    float2 A[16];
    // step 1: 4-pt FFT over n2 for each n1 (indices n1, n1+4, n1+8, n1+12)
#pragma unroll
    for (int n1 = 0; n1 < 4; n1++)
        bf4<FWD>(z[n1], z[n1 + 4], z[n1 + 8], z[n1 + 12],
                 A[n1 * 4 + 0], A[n1 * 4 + 1], A[n1 * 4 + 2], A[n1 * 4 + 3]);
    // step 2: A[n1][k2] *= w16^{n1*k2};  w16^k = (cos(k pi/8), S*sin(k pi/8))
    A[5]  = cmul(A[5],  make_float2( C1,  S * S1));   // w^1
    A[6]  = cmul(A[6],  make_float2( R,   S * R ));   // w^2
    A[7]  = cmul(A[7],  make_float2( S1,  S * C1));   // w^3
    A[9]  = cmul(A[9],  make_float2( R,   S * R ));   // w^2
    A[10] = make_float2(-S * A[10].y, S * A[10].x);   // w^4 = (0, S)
    A[11] = cmul(A[11], make_float2(-R,   S * R ));   // w^6
    A[13] = cmul(A[13], make_float2( S1,  S * C1));   // w^3
    A[14] = cmul(A[14], make_float2(-R,   S * R ));   // w^6
    A[15] = cmul(A[15], make_float2(-C1, -S * S1));   // w^9
    // step 3: 4-pt FFT over n1 for each k2;  Z[k2 + 4*k1]
#pragma unroll
    for (int k2 = 0; k2 < 4; k2++)
        bf4<FWD>(A[k2], A[4 + k2], A[8 + k2], A[12 + k2],
                 z[k2], z[k2 + 4], z[k2 + 8], z[k2 + 12]);
}

// ---------------- radix-16 Stockham stage (batched) ----------------
// s = 16^i, m = TN/(16 s); twiddle = exp(S*2pi*i*p*r*s/TN), th0 = S*2pi*s/TN
template <bool FWD>
__global__ void __launch_bounds__(256) fft16_stage(int inIsB, int log2s, float th0) {
    int gid  = blockIdx.x * blockDim.x + threadIdx.x;
    int tid  = gid & 65535;                 // TN/16 = 65536 butterflies per batch
    int base = (gid >> 16) << LOG2TN;
    const float2* __restrict__ X = (inIsB ? g_Bb : g_A) + base;
    float2* __restrict__       Y = (inIsB ? g_A : g_Bb) + base;
    int s_ = 1 << log2s;
    int q  = tid & (s_ - 1);
    int p  = tid >> log2s;
    int m  = TN >> (log2s + 4);

    float2 z[16];
#pragma unroll
    for (int j = 0; j < 16; j++) z[j] = X[q + ((p + j * m) << log2s)];

    fft16<FWD>(z);

    float ang = th0 * (float)p;
    float sn, cs;
    sincosf(ang, &sn, &cs);
    float2 w = make_float2(cs, sn), cur = w;
    int ob = q + ((p << 4) << log2s);
    Y[ob] = z[0];
#pragma unroll
    for (int r = 1; r < 16; r++) {
        Y[ob + (r << log2s)] = cmul(z[r], cur);
        cur = cmul(cur, w);
    }
}

// ---------------- persistent VMD iteration kernel ----------------
#define NBP 256
#define NTP 256
#define EP 16     // NBP*NTP*EP = 2^20

__global__ void __launch_bounds__(NTP, 2) vmd_persist() {
    int tid = threadIdx.x;
    int gid = blockIdx.x * NTP + tid;

    // f_hat and lambda live in registers for all 50 iterations
    float fhx[EP], fhy[EP], lax[EP], lay[EP];
#pragma unroll
    for (int e = 0; e < EP; e++) {
        float2 v = g_Bb[e * 65536 + gid];
        fhx[e] = v.x; fhy[e] = v.y;
        lax[e] = 0.f; lay[e] = 0.f;
    }
    float om0 = g_om[0], om1 = g_om[1], om2 = g_om[2];
    float oD0 = om0, oD1 = om1, oD2 = om2;  // omega entering previous iteration

    __shared__ float  sred[8][NTP / 32];
    __shared__ double sPrev[8];
    __shared__ float  sOm[3];
    __shared__ int    sTerm;
    if (tid < 8) sPrev[tid] = 0.0;
    __syncthreads();

    const float FRC = 1.0f / 1048576.0f;

    for (int n = 0; n < 50; n++) {
        float a0 = 0.f, a1 = 0.f, a2 = 0.f, a3 = 0.f, a4 = 0.f, a5 = 0.f, a6 = 0.f, a7 = 0.f;
        bool doDiff  = (n > 0) && (n % 10 == 0);
        bool doStash = (n % 10 == 9) && (n < 49);

#pragma unroll
        for (int e = 0; e < EP; e++) {
            int t = e * 65536 + gid;
            float fr = fmaf((float)gid, FRC, (float)(e * 65536) * FRC - 0.5f);
            float d0 = fr - om0; d0 *= d0;
            float d1 = fr - om1; d1 *= d1;
            float d2 = fr - om2; d2 *= d2;
            float g0 = 1.0f / (1.0f + C_ALPHA * ((d0 + C_TAU2) + d1));
            float g1 = 1.0f / (1.0f + C_ALPHA * (((d1 + C_TAU2) + d0) + d2));
            float g2 = 1.0f / (1.0f + C_ALPHA * ((d2 + C_TAU2) + d1));
            float nr = fhx[e] - 0.5f * lax[e];
            float ni = fhy[e] - 0.5f * lay[e];
            float m2 = nr * nr + ni * ni;
            float p0 = m2 * g0 * g0;
            float p1 = m2 * g1 * g1;
            float p2 = m2 * g2 * g2;
            a0 += p0; a1 += p1; a2 += p2;
            a3 += p0 * fr; a4 += p1 * fr; a5 += p2 * fr;

            if (doDiff) {
                float2 lp = g_lamPrev[t];
                float q0 = fr - oD0; q0 *= q0;
                float q1 = fr - oD1; q1 *= q1;
                float q2 = fr - oD2; q2 *= q2;
                float h0 = 1.0f / (1.0f + C_ALPHA * ((q0 + C_TAU2) + q1));
                float h1 = 1.0f / (1.0f + C_ALPHA * (((q1 + C_TAU2) + q0) + q2));
                float h2 = 1.0f / (1.0f + C_ALPHA * ((q2 + C_TAU2) + q1));
                float mr = fhx[e] - 0.5f * lp.x;
                float mi = fhy[e] - 0.5f * lp.y;
                float ex0 = nr * g0 - mr * h0, ey0 = ni * g0 - mi * h0;
                float ex1 = nr * g1 - mr * h1, ey1 = ni * g1 - mi * h1;
                float ex2 = nr * g2 - mr * h2, ey2 = ni * g2 - mi * h2;
                a6 += ex0 * ex0 + ey0 * ey0 + ex1 * ex1 + ey1 * ey1 + ex2 * ex2 + ey2 * ey2;
                a7 += (mr * mr + mi * mi) * (h0 * h0 + h1 * h1 + h2 * h2);
            }
            if (doStash) g_lamPrev[t] = make_float2(lax[e], lay[e]);

            // dual ascent (invertible; inverted on termination to recover u)
            float G = g0 + g1 + g2;
            lax[e] = lax[e] + C_TAU * (nr * G - fhx[e]);
            lay[e] = lay[e] + C_TAU * (ni * G - fhy[e]);
        }

        // ---- block reduce 8 accumulators ----
        float vals[8] = {a0, a1, a2, a3, a4, a5, a6, a7};
#pragma unroll
        for (int i = 0; i < 8; i++) {
            float v = vals[i];
#pragma unroll
            for (int o = 16; o > 0; o >>= 1) v += __shfl_down_sync(0xffffffffu, v, o);
            vals[i] = v;
        }
        int wid = tid >> 5, lid = tid & 31;
        if (lid == 0) {
#pragma unroll
            for (int i = 0; i < 8; i++) sred[i][wid] = vals[i];
        }
        __syncthreads();
        if (tid < 8) {
            double s = 0.0;
#pragma unroll
            for (int w = 0; w < NTP / 32; w++) s += (double)sred[tid][w];
            atomicAdd(&g_accM[tid], s);
            __threadfence();
        }
        __syncthreads();

        // ---- grid barrier + redundant scalar update (every block computes identically) ----
        if (tid == 0) {
            atomicAdd(&g_ctr, 1u);
            unsigned target = (unsigned)NBP * (unsigned)(n + 1);
            const volatile unsigned* vc = (const volatile unsigned*)&g_ctr;
            while (*vc < target) { __nanosleep(32); }
            __threadfence();
            double T[8], it[8];
#pragma unroll
            for (int i = 0; i < 8; i++) {
                T[i]  = *((const volatile double*)&g_accM[i]);
                it[i] = T[i] - sPrev[i];
                sPrev[i] = T[i];
            }
            float on0 = (float)(it[3] / (it[0] + 1e-8));
            float on1 = (float)(it[4] / (it[1] + 1e-8));
            float on2 = (float)(it[5] / (it[2] + 1e-8));
            float odiff = (fabsf(on0 - on2) + fabsf(on1 - on0) + fabsf(on2 - on1)) * (1.0f / 3.0f);
            double udiff = (n == 0) ? (it[0] + it[1] + it[2]) / 1e-8
                                    : it[6] / (it[7] + 1e-8);
            int done = (n % 10 == 0) && (udiff < 1e-6) && (odiff < 1e-6f);
            sOm[0] = on0; sOm[1] = on1; sOm[2] = on2;
            sTerm = (done || n == 49) ? 1 : 0;
        }
        __syncthreads();

        if (sTerm) {
            // final u = u_new of this iteration = f(lambda entering, omega entering).
            // Recover entering lambda by inverting the update:
            //   la_new = la*(1 - tau*G/2) + tau*fh*(G-1)  =>  la = (la_new - tau*fh*(G-1))/(1 - tau*G/2)
#pragma unroll
            for (int e = 0; e < EP; e++) {
                int t = e * 65536 + gid;
                float fr = fmaf((float)gid, FRC, (float)(e * 65536) * FRC - 0.5f);
                float d0 = fr - om0; d0 *= d0;
                float d1 = fr - om1; d1 *= d1;
                float d2 = fr - om2; d2 *= d2;
                float g0 = 1.0f / (1.0f + C_ALPHA * ((d0 + C_TAU2) + d1));
                float g1 = 1.0f / (1.0f + C_ALPHA * (((d1 + C_TAU2) + d0) + d2));
                float g2 = 1.0f / (1.0f + C_ALPHA * ((d2 + C_TAU2) + d1));
                float G  = g0 + g1 + g2;
                float inv = 1.0f / (1.0f - 0.5f * C_TAU * G);
                float lox = (lax[e] - C_TAU * fhx[e] * (G - 1.0f)) * inv;
                float loy = (lay[e] - C_TAU * fhy[e] * (G - 1.0f)) * inv;
                float nr = fhx[e] - 0.5f * lox;
                float ni = fhy[e] - 0.5f * loy;
                g_A[t]          = make_float2(nr * g0, ni * g0);
                g_A[TN + t]     = make_float2(nr * g1, ni * g1);
                g_A[2 * TN + t] = make_float2(nr * g2, ni * g2);
            }
            break;
        }
        // advance omega history
        oD0 = om0; oD1 = om1; oD2 = om2;
        om0 = sOm[0]; om1 = sOm[1]; om2 = sOm[2];
        __syncthreads();   // protect sOm/sTerm reuse next iteration
    }
}

// imfs[k,n] = (-1)^n * Re(ifft(u_k)),  scale 1/TN applied here; inverse result in g_Bb
__global__ void out_kernel(float* __restrict__ out) {
    int i = blockIdx.x * blockDim.x + threadIdx.x;
    int t = i & (TN - 1);
    float s = (t & 1) ? -(1.0f / 1048576.0f) : (1.0f / 1048576.0f);
    out[i] = g_Bb[i].x * s;
}

// ---------------- launch ----------------
extern "C" void kernel_launch(void* const* d_in, const int* in_sizes, int n_in,
                              void* d_out, int out_size) {
    const float* x   = (const float*)d_in[0];
    const float* om0 = (const float*)d_in[1];
    float* out = (float*)d_out;

    init_kernel<<<1, 32>>>(om0);
    pack_kernel<<<TN / 256, 256>>>(x);

    // forward FFT of (-1)^n x : 5 radix-16 stages, A->B->A->B->A->B (ends in g_Bb)
    for (int i = 0; i < 5; i++) {
        float th0 = (float)(-2.0 * PI_D * (double)(1 << (4 * i)) / (double)TN);
        fft16_stage<true><<<256, 256>>>(i & 1, 4 * i, th0);
    }

    vmd_persist<<<NBP, NTP>>>();

    // inverse FFT (batch K=3): 5 radix-16 stages with conjugate twiddles, ends in g_Bb
    for (int i = 0; i < 5; i++) {
        float th0 = (float)(2.0 * PI_D * (double)(1 << (4 * i)) / (double)TN);
        fft16_stage<false><<<768, 256>>>(i & 1, 4 * i, th0);
    }
    out_kernel<<<3 * TN / 256, 256>>>(out);
}